// round 9
// baseline (speedup 1.0000x reference)
#include <cuda_runtime.h>

#define NCLS   10
#define NTHR   256
#define WARPS  8
#define NBLK   1184  // 8 CTAs/SM x 148 SMs -> 64 warps/SM (warp cap), one resident wave

__device__ float g_sum[NCLS];
__device__ float g_cnt[NCLS];
__device__ unsigned int g_done;   // zero-initialized; reset by finalizing block

__device__ __forceinline__ void acc1(float o, float t, int m, float2* lane_base) {
    float d  = o - t;
    float mf = (float)m;
    int   c  = (int)t;
    float dm = d * mf;
    float2 v = lane_base[c * 32];
    v.x = fmaf(d, dm, v.x);
    v.y += mf;
    lane_base[c * 32] = v;
}

__global__ __launch_bounds__(NTHR) void loss_kernel(
    const float4* __restrict__ o4,
    const float4* __restrict__ t4,
    const int4*   __restrict__ m4,
    const float*  __restrict__ o_s,
    const float*  __restrict__ t_s,
    const int*    __restrict__ m_s,
    float* __restrict__ out,
    int n4, int n, int out_size)
{
    // Per-warp, per-lane-column accumulators: acc[warp][cls][lane] = (sum, cnt).
    // Lane owns its column -> plain RMW, no atomics. Word index =
    // (cls*64 + 2*lane) mod 32 = 2*lane mod 32 -> conflict-free per half-warp
    // phase regardless of class divergence. 20KB/CTA -> warp-cap-limited occ.
    __shared__ float2 acc[WARPS][NCLS][32];
    __shared__ float s_le[NCLS];
    __shared__ unsigned int s_last;

    int tid = threadIdx.x;
    int w = tid >> 5, l = tid & 31;

    #pragma unroll
    for (int c = 0; c < NCLS; ++c) acc[w][c][l] = make_float2(0.f, 0.f);
    __syncthreads();

    float2* lane_base = &acc[w][0][l];   // class stride = 32 float2

    int idx    = blockIdx.x * NTHR + tid;
    int stride = gridDim.x * NTHR;

    // Measured-best loop shape (R6): 3 independent LDG.128 batched per iter.
    // Deeper front-batching regressed (R4); split accumulators regressed (R8).
    for (int i = idx; i < n4; i += stride) {
        float4 o = o4[i];
        float4 t = t4[i];
        int4   m = m4[i];
        acc1(o.x, t.x, m.x, lane_base);
        acc1(o.y, t.y, m.y, lane_base);
        acc1(o.z, t.z, m.z, lane_base);
        acc1(o.w, t.w, m.w, lane_base);
    }

    // Scalar tail (defensive; n = 16.78M is divisible by 4 so normally empty).
    if (blockIdx.x == 0) {
        for (int k = n4 * 4 + tid; k < n; k += NTHR)
            acc1(o_s[k], t_s[k], m_s[k], lane_base);
    }

    __syncthreads();

    // Block reduction: 320 slots (cls, lane); lane dim reduces via shfl in-warp.
    for (int s = tid; s < NCLS * 32; s += NTHR) {
        int c = s >> 5, ll = s & 31;
        float sum = 0.f, cnt = 0.f;
        #pragma unroll
        for (int ww = 0; ww < WARPS; ++ww) {
            float2 v = acc[ww][c][ll];
            sum += v.x; cnt += v.y;
        }
        #pragma unroll
        for (int off = 16; off; off >>= 1) {
            sum += __shfl_down_sync(0xffffffffu, sum, off);
            cnt += __shfl_down_sync(0xffffffffu, cnt, off);
        }
        if (ll == 0) {
            atomicAdd(&g_sum[c], sum);
            atomicAdd(&g_cnt[c], cnt);
        }
    }

    // Last-block-done finalize (single launch; graph-replay safe via reset).
    __threadfence();
    __syncthreads();
    if (tid == 0)
        s_last = (atomicAdd(&g_done, 1u) == (unsigned)gridDim.x - 1u) ? 1u : 0u;
    __syncthreads();

    if (s_last) {
        if (tid < NCLS) {
            float s = g_sum[tid], nn = g_cnt[tid];
            float v = (nn > 0.f) ? s / fmaxf(nn, 1.f) : 0.f;
            s_le[tid] = v;
            if (1 + tid  < out_size) out[1 + tid]  = v;   // loss_each
            if (11 + tid < out_size) out[11 + tid] = nn;  // class_n
            // Reset for next graph replay (restores zero-initialized state).
            g_sum[tid] = 0.f;
            g_cnt[tid] = 0.f;
        }
        __syncthreads();
        if (tid == 0) {
            float loss = 0.f;
            #pragma unroll
            for (int c = 0; c < NCLS; ++c) loss += 0.1f * s_le[c];
            if (out_size > 0) out[0] = loss;
            g_done = 0u;
        }
        // Zero any tail beyond the 21 expected outputs (d_out is poisoned).
        for (int k = 21 + tid; k < out_size; k += NTHR) out[k] = 0.f;
    }
}

extern "C" void kernel_launch(void* const* d_in, const int* in_sizes, int n_in,
                              void* d_out, int out_size) {
    const float* outputs = (const float*)d_in[0];
    const float* targets = (const float*)d_in[1];
    const int*   mask    = (const int*)d_in[2];
    int n  = in_sizes[0];
    int n4 = n >> 2;

    loss_kernel<<<NBLK, NTHR>>>(
        (const float4*)outputs, (const float4*)targets, (const int4*)mask,
        outputs, targets, mask, (float*)d_out, n4, n, out_size);
}

// round 10
// speedup vs baseline: 1.0766x; 1.0766x over previous
#include <cuda_runtime.h>

#define NCLS   10
#define NTHR   256
#define WARPS  8
#define NBLK   888   // 6 CTAs/SM x 148 = measured-best 48 warps/SM (R6)

__device__ float g_sum[NCLS];
__device__ float g_cnt[NCLS];
__device__ unsigned int g_done;   // zero-initialized; reset by finalizing block

__device__ __forceinline__ void acc1(float o, float t, int m, float2* lane_base) {
    float d  = o - t;
    float mf = (float)m;
    int   c  = (int)t;
    float dm = d * mf;
    float2 v = lane_base[c * 32];
    v.x = fmaf(d, dm, v.x);
    v.y += mf;
    lane_base[c * 32] = v;
}

__device__ __forceinline__ void acc4(const float4& o, const float4& t, const int4& m,
                                     float2* lane_base) {
    acc1(o.x, t.x, m.x, lane_base);
    acc1(o.y, t.y, m.y, lane_base);
    acc1(o.z, t.z, m.z, lane_base);
    acc1(o.w, t.w, m.w, lane_base);
}

__global__ __launch_bounds__(NTHR, 6) void loss_kernel(
    const float4* __restrict__ o4,
    const float4* __restrict__ t4,
    const int4*   __restrict__ m4,
    const float*  __restrict__ o_s,
    const float*  __restrict__ t_s,
    const int*    __restrict__ m_s,
    float* __restrict__ out,
    int n4, int n, int out_size)
{
    // Per-warp, per-lane-column accumulators: acc[warp][cls][lane] = (sum, cnt).
    // Lane owns its column -> plain RMW, no atomics. Word index =
    // 2*lane mod 32 -> conflict-free per half-warp phase.
    __shared__ float2 acc[WARPS][NCLS][32];
    __shared__ float s_le[NCLS];
    __shared__ unsigned int s_last;

    int tid = threadIdx.x;
    int w = tid >> 5, l = tid & 31;

    #pragma unroll
    for (int c = 0; c < NCLS; ++c) acc[w][c][l] = make_float2(0.f, 0.f);
    __syncthreads();

    float2* lane_base = &acc[w][0][l];   // class stride = 32 float2

    int idx    = blockIdx.x * NTHR + tid;
    int stride = gridDim.x * NTHR;

    // Register prefetch pipeline: issue iter k+1's 3 LDG.128 BEFORE consuming
    // iter k's registers, so the ~140cyc smem RMW chain overlaps the loads'
    // memory latency instead of serializing with it. MLP_p1 stays 3 (batching
    // 6 regressed in R4; warp count held at R6's measured optimum).
    int i = idx;
    if (i < n4) {
        float4 o = o4[i];
        float4 t = t4[i];
        int4   m = m4[i];
        for (; i + stride < n4; i += stride) {
            float4 o2 = o4[i + stride];
            float4 t2 = t4[i + stride];
            int4   m2 = m4[i + stride];
            acc4(o, t, m, lane_base);
            o = o2; t = t2; m = m2;
        }
        acc4(o, t, m, lane_base);   // drain last prefetched iter
    }

    // Scalar tail (defensive; n = 16.78M is divisible by 4 so normally empty).
    if (blockIdx.x == 0) {
        for (int k = n4 * 4 + tid; k < n; k += NTHR)
            acc1(o_s[k], t_s[k], m_s[k], lane_base);
    }

    __syncthreads();

    // Block reduction: 320 slots (cls, lane); lane dim reduces via shfl in-warp.
    for (int s = tid; s < NCLS * 32; s += NTHR) {
        int c = s >> 5, ll = s & 31;
        float sum = 0.f, cnt = 0.f;
        #pragma unroll
        for (int ww = 0; ww < WARPS; ++ww) {
            float2 v = acc[ww][c][ll];
            sum += v.x; cnt += v.y;
        }
        #pragma unroll
        for (int off = 16; off; off >>= 1) {
            sum += __shfl_down_sync(0xffffffffu, sum, off);
            cnt += __shfl_down_sync(0xffffffffu, cnt, off);
        }
        if (ll == 0) {
            atomicAdd(&g_sum[c], sum);
            atomicAdd(&g_cnt[c], cnt);
        }
    }

    // Last-block-done finalize (single launch; graph-replay safe via reset).
    __threadfence();
    __syncthreads();
    if (tid == 0)
        s_last = (atomicAdd(&g_done, 1u) == (unsigned)gridDim.x - 1u) ? 1u : 0u;
    __syncthreads();

    if (s_last) {
        if (tid < NCLS) {
            float s = g_sum[tid], nn = g_cnt[tid];
            float v = (nn > 0.f) ? s / fmaxf(nn, 1.f) : 0.f;
            s_le[tid] = v;
            if (1 + tid  < out_size) out[1 + tid]  = v;   // loss_each
            if (11 + tid < out_size) out[11 + tid] = nn;  // class_n
            // Reset for next graph replay (restores zero-initialized state).
            g_sum[tid] = 0.f;
            g_cnt[tid] = 0.f;
        }
        __syncthreads();
        if (tid == 0) {
            float loss = 0.f;
            #pragma unroll
            for (int c = 0; c < NCLS; ++c) loss += 0.1f * s_le[c];
            if (out_size > 0) out[0] = loss;
            g_done = 0u;
        }
        // Zero any tail beyond the 21 expected outputs (d_out is poisoned).
        for (int k = 21 + tid; k < out_size; k += NTHR) out[k] = 0.f;
    }
}

extern "C" void kernel_launch(void* const* d_in, const int* in_sizes, int n_in,
                              void* d_out, int out_size) {
    const float* outputs = (const float*)d_in[0];
    const float* targets = (const float*)d_in[1];
    const int*   mask    = (const int*)d_in[2];
    int n  = in_sizes[0];
    int n4 = n >> 2;

    loss_kernel<<<NBLK, NTHR>>>(
        (const float4*)outputs, (const float4*)targets, (const int4*)mask,
        outputs, targets, mask, (float*)d_out, n4, n, out_size);
}